// round 5
// baseline (speedup 1.0000x reference)
#include <cuda_runtime.h>

// SNN LIF spike-count — HBM-streaming (256 MiB read-once).
// R5: 3-buffer rotation, load-ahead = 2 batches (8 LDG.128 in flight per
// warp while consuming). asm-volatile loads pin issue order; the 3-way
// rotation forces buffer lifetimes to overlap so ptxas can't collapse
// them (expect regs ~70, capped by __launch_bounds__(128,7)).

#define ALPHA 0.9f
#define BETA  0.95f

#define LOADCS4(dst, ptr)                                             \
    asm volatile("ld.global.cs.v4.f32 {%0,%1,%2,%3}, [%4];"           \
                 : "=f"((dst).x), "=f"((dst).y),                      \
                   "=f"((dst).z), "=f"((dst).w)                       \
                 : "l"(ptr))

__device__ __forceinline__ void lif_step(float xv, float& syn, float& mem, float& cnt)
{
    syn = fmaf(ALPHA, syn, xv);
    mem = fmaf(BETA,  mem, syn);
    float s = (mem > 1.0f) ? 1.0f : 0.0f;
    cnt += s;
    mem *= (1.0f - s);
}

__device__ __forceinline__ void load4(float4* buf, const float4* p, long ls)
{
    LOADCS4(buf[0], p);
    LOADCS4(buf[1], p + ls);
    LOADCS4(buf[2], p + 2 * ls);
    LOADCS4(buf[3], p + 3 * ls);
}

__device__ __forceinline__ void consume4(const float4* buf,
                                         float4& syn, float4& mem, float4& cnt)
{
    #pragma unroll
    for (int u = 0; u < 4; u++) {
        lif_step(buf[u].x, syn.x, mem.x, cnt.x);
        lif_step(buf[u].y, syn.y, mem.y, cnt.y);
        lif_step(buf[u].z, syn.z, mem.z, cnt.z);
        lif_step(buf[u].w, syn.w, mem.w, cnt.w);
    }
}

__global__ void __launch_bounds__(128, 7)
snn_count_kernel(const float4* __restrict__ x,
                 const float4* __restrict__ mem0,
                 const float4* __restrict__ syn0,
                 const float4* __restrict__ count0,
                 float4* __restrict__ out,
                 int stride4,   // (B*N)/4
                 int T)         // T = 128: 32 batches of 4
{
    int i = blockIdx.x * blockDim.x + threadIdx.x;
    if (i >= stride4) return;

    float4 syn = syn0[i];
    float4 mem = mem0[i];
    float4 cnt = count0[i];

    const float4* xp = x + i;
    long ls = stride4;

    float4 bufA[4], bufB[4], bufC[4];

    // Prologue: batches 0,1 in flight.
    load4(bufA, xp, ls);            xp += 4 * ls;
    load4(bufB, xp, ls);            xp += 4 * ls;

    // 30 remaining batches to load, 30 to consume in the loop (10 triples).
    for (int iter = 0; iter < 10; iter++) {
        load4(bufC, xp, ls);        xp += 4 * ls;
        consume4(bufA, syn, mem, cnt);

        load4(bufA, xp, ls);        xp += 4 * ls;
        consume4(bufB, syn, mem, cnt);

        load4(bufB, xp, ls);        xp += 4 * ls;
        consume4(bufC, syn, mem, cnt);
    }

    // Epilogue: A,B hold batches 30,31.
    consume4(bufA, syn, mem, cnt);
    consume4(bufB, syn, mem, cnt);

    out[i] = cnt;
}

extern "C" void kernel_launch(void* const* d_in, const int* in_sizes, int n_in,
                              void* d_out, int out_size)
{
    const float* x      = (const float*)d_in[0];   // (T, B, N)
    const float* mem0   = (const float*)d_in[1];   // (B, N)
    const float* syn0   = (const float*)d_in[2];   // (B, N)
    const float* count0 = (const float*)d_in[3];   // (B, N)
    float* out          = (float*)d_out;           // (B, N)

    int BN = in_sizes[1];           // B*N
    int T  = in_sizes[0] / BN;      // timesteps

    int stride4 = BN / 4;
    int threads = 128;
    int blocks  = (stride4 + threads - 1) / threads;

    snn_count_kernel<<<blocks, threads>>>(
        (const float4*)x, (const float4*)mem0, (const float4*)syn0,
        (const float4*)count0, (float4*)out, stride4, T);
}